// round 14
// baseline (speedup 1.0000x reference)
#include <cuda_runtime.h>
#include <cuda_fp16.h>
#include <cuda_bf16.h>

// Problem constants (from reference: N=100000, F=128, Fo=64, E=1600000)
#define NMAX 100000
#define EMAX 1600000
#define FDIM 128
#define FO   64

__device__ int g_cnt[NMAX];                 // #edges with dst=i (no self loop)
__device__ int g_off[NMAX];                 // exclusive CSR offsets
__device__ int g_cur[NMAX];                 // bin cursors
__device__ int g_bsum[512];                 // scan block sums
__device__ int g_srcs[EMAX];                // CSR: srcs grouped by dst
__device__ __align__(16) __half g_hs[NMAX * FO];   // fp16 messages h[i]*dinv[i]

// ---------------------------------------------------------------------------
__global__ void k_zero(int N) {
    int i = blockIdx.x * blockDim.x + threadIdx.x;
    if (i < N) g_cnt[i] = 0;
}

// count edges per dst (4 edges/thread, int4)
__global__ void k_cnt(const int* __restrict__ ei, int E) {
    int t = blockIdx.x * blockDim.x + threadIdx.x;
    int e0 = t * 4;
    if (e0 + 3 < E) {
        int4 d = *(const int4*)(ei + E + e0);
        atomicAdd(&g_cnt[d.x], 1);
        atomicAdd(&g_cnt[d.y], 1);
        atomicAdd(&g_cnt[d.z], 1);
        atomicAdd(&g_cnt[d.w], 1);
    } else {
        for (int e = e0; e < E; e++) atomicAdd(&g_cnt[ei[E + e]], 1);
    }
}

// ---- 3-phase exclusive scan of g_cnt -> g_off ------------------------------
__global__ void k_scan1(int N) {
    __shared__ int sh[256];
    int t = threadIdx.x;
    int i = blockIdx.x * 256 + t;
    int v = (i < N) ? g_cnt[i] : 0;
    sh[t] = v;
    __syncthreads();
    #pragma unroll
    for (int o = 1; o < 256; o <<= 1) {
        int add = (t >= o) ? sh[t - o] : 0;
        __syncthreads();
        sh[t] += add;
        __syncthreads();
    }
    if (i < N) g_off[i] = sh[t] - v;           // exclusive within block
    if (t == 255) g_bsum[blockIdx.x] = sh[255];
}

__global__ void k_scan2(int nb) {
    __shared__ int sh[512];
    int t = threadIdx.x;
    int v = (t < nb) ? g_bsum[t] : 0;
    sh[t] = v;
    __syncthreads();
    #pragma unroll
    for (int o = 1; o < 512; o <<= 1) {
        int add = (t >= o) ? sh[t - o] : 0;
        __syncthreads();
        sh[t] += add;
        __syncthreads();
    }
    if (t < nb) g_bsum[t] = sh[t] - v;         // exclusive block offsets
}

__global__ void k_scan3(int N) {
    int i = blockIdx.x * blockDim.x + threadIdx.x;
    if (i < N) {
        int o = g_off[i] + g_bsum[i >> 8];
        g_off[i] = o;
        g_cur[i] = o;
    }
}

// bin: scatter src ids into CSR slots (int atomics, 4B each)
__global__ void k_bin(const int* __restrict__ ei, int E) {
    int t = blockIdx.x * blockDim.x + threadIdx.x;
    int e0 = t * 4;
    if (e0 + 3 < E) {
        int4 s4 = *(const int4*)(ei + e0);
        int4 d4 = *(const int4*)(ei + E + e0);
        g_srcs[atomicAdd(&g_cur[d4.x], 1)] = s4.x;
        g_srcs[atomicAdd(&g_cur[d4.y], 1)] = s4.y;
        g_srcs[atomicAdd(&g_cur[d4.z], 1)] = s4.z;
        g_srcs[atomicAdd(&g_cur[d4.w], 1)] = s4.w;
    } else {
        for (int e = e0; e < E; e++)
            g_srcs[atomicAdd(&g_cur[ei[E + e]], 1)] = ei[e];
    }
}

// ---------------------------------------------------------------------------
// K gemm: hs(fp16) = (x @ W^T) * dinv  via HMMA m16n8k16 (R12 config, proven).
// dinv from g_cnt (+1 self loop). Writes only g_hs now.
#define SA 136

__global__ __launch_bounds__(256) void k_gemm(const float* __restrict__ x,
                                              const float* __restrict__ W,
                                              int N) {
    extern __shared__ __half smh[];
    __half* A_sh = smh;                 // [128][SA]
    __half* B_sh = smh + 128 * SA;      // [64][SA]

    int tid = threadIdx.x;
    int row0 = blockIdx.x * 128;

    #pragma unroll
    for (int i = tid; i < 64 * 32; i += 256) {
        int n  = i >> 5;
        int k4 = (i & 31) << 2;
        float4 v = *(const float4*)(W + n * FDIM + k4);
        __half* p = B_sh + n * SA + k4;
        *(__half2*)(p)     = __floats2half2_rn(v.x, v.y);
        *(__half2*)(p + 2) = __floats2half2_rn(v.z, v.w);
    }

    #pragma unroll
    for (int i = tid; i < 128 * 32; i += 256) {
        int r  = i >> 5;
        int k4 = (i & 31) << 2;
        int gr = row0 + r;
        float4 v = (gr < N) ? *(const float4*)(x + (long)gr * FDIM + k4)
                            : make_float4(0.f, 0.f, 0.f, 0.f);
        __half* p = A_sh + r * SA + k4;
        *(__half2*)(p)     = __floats2half2_rn(v.x, v.y);
        *(__half2*)(p + 2) = __floats2half2_rn(v.z, v.w);
    }
    __syncthreads();

    int warp = tid >> 5;
    int lane = tid & 31;
    int gid  = lane >> 2;
    int tig  = lane & 3;
    int mrow = warp * 16;

    float acc[8][4];
    #pragma unroll
    for (int nt = 0; nt < 8; nt++)
        #pragma unroll
        for (int j = 0; j < 4; j++) acc[nt][j] = 0.f;

    #pragma unroll
    for (int kt = 0; kt < 8; kt++) {
        int kb = kt * 16 + tig * 2;
        const __half* ar0 = A_sh + (mrow + gid) * SA + kb;
        const __half* ar1 = ar0 + 8 * SA;
        unsigned a0 = *(const unsigned*)(ar0);
        unsigned a1 = *(const unsigned*)(ar1);
        unsigned a2 = *(const unsigned*)(ar0 + 8);
        unsigned a3 = *(const unsigned*)(ar1 + 8);
        #pragma unroll
        for (int nt = 0; nt < 8; nt++) {
            const __half* br = B_sh + (nt * 8 + gid) * SA + kb;
            unsigned b0 = *(const unsigned*)(br);
            unsigned b1 = *(const unsigned*)(br + 8);
            asm("mma.sync.aligned.m16n8k16.row.col.f32.f16.f16.f32 "
                "{%0,%1,%2,%3}, {%4,%5,%6,%7}, {%8,%9}, {%0,%1,%2,%3};"
                : "+f"(acc[nt][0]), "+f"(acc[nt][1]),
                  "+f"(acc[nt][2]), "+f"(acc[nt][3])
                : "r"(a0), "r"(a1), "r"(a2), "r"(a3), "r"(b0), "r"(b1));
        }
    }

    int r0 = row0 + mrow + gid;
    int r1 = r0 + 8;
    float dinv0 = (r0 < N) ? rsqrtf((float)g_cnt[r0] + 1.0f) : 0.f;
    float dinv1 = (r1 < N) ? rsqrtf((float)g_cnt[r1] + 1.0f) : 0.f;
    #pragma unroll
    for (int nt = 0; nt < 8; nt++) {
        int c = nt * 8 + tig * 2;
        if (r0 < N)
            *(__half2*)(g_hs + (long)r0 * FO + c) =
                __floats2half2_rn(acc[nt][0] * dinv0, acc[nt][1] * dinv0);
        if (r1 < N)
            *(__half2*)(g_hs + (long)r1 * FO + c) =
                __floats2half2_rn(acc[nt][2] * dinv1, acc[nt][3] * dinv1);
    }
}

// ---------------------------------------------------------------------------
// K aggfinal: warp per node. fp32-accumulate self + CSR neighbors (gather
// only, no atomics), then fused relu -> dot(W_lin) -> sigmoid epilogue.
__global__ __launch_bounds__(256) void k_aggfinal(const float* __restrict__ Wl,
                                                  const float* __restrict__ bl,
                                                  const float* __restrict__ bconv,
                                                  float* __restrict__ out, int N) {
    int node = (int)((blockIdx.x * blockDim.x + threadIdx.x) >> 5);
    int lane = threadIdx.x & 31;
    if (node >= N) return;

    int cnt = g_cnt[node];
    int off = g_off[node];

    float2 acc = __half22float2(
        *((const __half2*)(g_hs + (long)node * FO) + lane));   // self loop

    for (int base = 0; base < cnt; base += 32) {
        int m = cnt - base; if (m > 32) m = 32;
        int s = 0;
        if (lane < m) s = __ldg(g_srcs + off + base + lane);
        for (int j = 0; j < m; j++) {
            int sj = __shfl_sync(0xFFFFFFFFu, s, j);
            float2 mv = __half22float2(
                __ldg((const __half2*)(g_hs + (long)sj * FO) + lane));
            acc.x += mv.x;
            acc.y += mv.y;
        }
    }

    float dinv = rsqrtf((float)cnt + 1.0f);
    float2 wv = *(const float2*)&Wl[lane * 2];
    float2 bc = *(const float2*)&bconv[lane * 2];
    float v0 = fmaxf(fmaf(acc.x, dinv, bc.x), 0.0f);
    float v1 = fmaxf(fmaf(acc.y, dinv, bc.y), 0.0f);
    float s = v0 * wv.x + v1 * wv.y;

    #pragma unroll
    for (int o = 16; o; o >>= 1) s += __shfl_xor_sync(0xFFFFFFFFu, s, o);

    if (lane == 0)
        out[node] = 1.0f / (1.0f + expf(-(s + bl[0])));
}

// ---------------------------------------------------------------------------
extern "C" void kernel_launch(void* const* d_in, const int* in_sizes, int n_in,
                              void* d_out, int out_size) {
    const float* x   = (const float*)d_in[0];
    const int*   ei  = (const int*)  d_in[1];
    const float* Wc  = (const float*)d_in[2];
    const float* bc  = (const float*)d_in[3];
    const float* Wl  = (const float*)d_in[4];
    const float* bl  = (const float*)d_in[5];
    float*       out = (float*)d_out;

    int N = in_sizes[0] / FDIM;
    int E = in_sizes[1] / 2;
    if (N > NMAX) N = NMAX;
    if (E > EMAX) E = EMAX;
    int nb = (N + 255) / 256;   // scan blocks (<=512)

    const int GEMM_SMEM = (128 + 64) * SA * (int)sizeof(__half);   // 52224 B
    cudaFuncSetAttribute(k_gemm, cudaFuncAttributeMaxDynamicSharedMemorySize,
                         GEMM_SMEM);

    // side stream + events for the capture-legal fork/join (created per call;
    // kernel_launch runs only twice — correctness + capture — trivial leak,
    // no device memory involved)
    cudaStream_t s2;
    cudaEvent_t ev_fork, ev_join;
    cudaStreamCreateWithFlags(&s2, cudaStreamNonBlocking);
    cudaEventCreateWithFlags(&ev_fork, cudaEventDisableTiming);
    cudaEventCreateWithFlags(&ev_join, cudaEventDisableTiming);

    // main chain: zero counts, count dst degrees
    k_zero<<<(N + 255) / 256, 256>>>(N);
    k_cnt <<<((E + 3) / 4 + 255) / 256, 256>>>(ei, E);

    // fork: CSR build (scan + bin) on s2, concurrent with gemm on main stream
    cudaEventRecord(ev_fork, 0);
    cudaStreamWaitEvent(s2, ev_fork, 0);
    k_scan1<<<nb, 256, 0, s2>>>(N);
    k_scan2<<<1, 512, 0, s2>>>(nb);
    k_scan3<<<(N + 255) / 256, 256, 0, s2>>>(N);
    k_bin  <<<((E + 3) / 4 + 255) / 256, 256, 0, s2>>>(ei, E);
    cudaEventRecord(ev_join, s2);

    k_gemm<<<(N + 127) / 128, 256, GEMM_SMEM>>>(x, Wc, N);

    // join, then fused aggregate + classifier head
    cudaStreamWaitEvent(0, ev_join, 0);
    k_aggfinal<<<(N + 7) / 8, 256>>>(Wl, bl, bc, out, N);
}

// round 15
// speedup vs baseline: 1.2460x; 1.2460x over previous
#include <cuda_runtime.h>
#include <cuda_fp16.h>
#include <cuda_bf16.h>

// Problem constants (from reference: N=100000, F=128, Fo=64, E=1600000)
#define NMAX 100000
#define FDIM 128
#define FO   64

__device__ __align__(16) float  g_deg[NMAX];
__device__ __align__(16) __half g_hs [NMAX * FO];  // h, then h*dinv after k_scale
__device__ __align__(16) __half g_tmp[NMAX * FO];  // fp16 aggregate (init by k_scale)

// ---------------------------------------------------------------------------
__global__ void k_deg_init(int N) {
    int i = blockIdx.x * blockDim.x + threadIdx.x;
    if (i < N) g_deg[i] = 1.0f;
}

__global__ void k_deg_acc(const int* __restrict__ ei, int E) {
    int t = blockIdx.x * blockDim.x + threadIdx.x;
    int e0 = t * 4;
    if (e0 + 3 < E) {
        int4 d = *(const int4*)(ei + E + e0);
        atomicAdd(&g_deg[d.x], 1.0f);
        atomicAdd(&g_deg[d.y], 1.0f);
        atomicAdd(&g_deg[d.z], 1.0f);
        atomicAdd(&g_deg[d.w], 1.0f);
    } else {
        for (int e = e0; e < E; e++) atomicAdd(&g_deg[ei[E + e]], 1.0f);
    }
}

// ---------------------------------------------------------------------------
// K gemm_h: g_hs(fp16) = x @ W^T  (UNSCALED — independent of the degree pass,
// so it can run concurrently with it). HMMA m16n8k16, R12 config (proven).
#define SA 136

__global__ __launch_bounds__(256) void k_gemm_h(const float* __restrict__ x,
                                                const float* __restrict__ W,
                                                int N) {
    extern __shared__ __half smh[];
    __half* A_sh = smh;                 // [128][SA]
    __half* B_sh = smh + 128 * SA;      // [64][SA]

    int tid = threadIdx.x;
    int row0 = blockIdx.x * 128;

    #pragma unroll
    for (int i = tid; i < 64 * 32; i += 256) {
        int n  = i >> 5;
        int k4 = (i & 31) << 2;
        float4 v = *(const float4*)(W + n * FDIM + k4);
        __half* p = B_sh + n * SA + k4;
        *(__half2*)(p)     = __floats2half2_rn(v.x, v.y);
        *(__half2*)(p + 2) = __floats2half2_rn(v.z, v.w);
    }

    #pragma unroll
    for (int i = tid; i < 128 * 32; i += 256) {
        int r  = i >> 5;
        int k4 = (i & 31) << 2;
        int gr = row0 + r;
        float4 v = (gr < N) ? *(const float4*)(x + (long)gr * FDIM + k4)
                            : make_float4(0.f, 0.f, 0.f, 0.f);
        __half* p = A_sh + r * SA + k4;
        *(__half2*)(p)     = __floats2half2_rn(v.x, v.y);
        *(__half2*)(p + 2) = __floats2half2_rn(v.z, v.w);
    }
    __syncthreads();

    int warp = tid >> 5;
    int lane = tid & 31;
    int gid  = lane >> 2;
    int tig  = lane & 3;
    int mrow = warp * 16;

    float acc[8][4];
    #pragma unroll
    for (int nt = 0; nt < 8; nt++)
        #pragma unroll
        for (int j = 0; j < 4; j++) acc[nt][j] = 0.f;

    #pragma unroll
    for (int kt = 0; kt < 8; kt++) {
        int kb = kt * 16 + tig * 2;
        const __half* ar0 = A_sh + (mrow + gid) * SA + kb;
        const __half* ar1 = ar0 + 8 * SA;
        unsigned a0 = *(const unsigned*)(ar0);
        unsigned a1 = *(const unsigned*)(ar1);
        unsigned a2 = *(const unsigned*)(ar0 + 8);
        unsigned a3 = *(const unsigned*)(ar1 + 8);
        #pragma unroll
        for (int nt = 0; nt < 8; nt++) {
            const __half* br = B_sh + (nt * 8 + gid) * SA + kb;
            unsigned b0 = *(const unsigned*)(br);
            unsigned b1 = *(const unsigned*)(br + 8);
            asm("mma.sync.aligned.m16n8k16.row.col.f32.f16.f16.f32 "
                "{%0,%1,%2,%3}, {%4,%5,%6,%7}, {%8,%9}, {%0,%1,%2,%3};"
                : "+f"(acc[nt][0]), "+f"(acc[nt][1]),
                  "+f"(acc[nt][2]), "+f"(acc[nt][3])
                : "r"(a0), "r"(a1), "r"(a2), "r"(a3), "r"(b0), "r"(b1));
        }
    }

    int r0 = row0 + mrow + gid;
    int r1 = r0 + 8;
    #pragma unroll
    for (int nt = 0; nt < 8; nt++) {
        int c = nt * 8 + tig * 2;
        if (r0 < N)
            *(__half2*)(g_hs + (long)r0 * FO + c) =
                __floats2half2_rn(acc[nt][0], acc[nt][1]);
        if (r1 < N)
            *(__half2*)(g_hs + (long)r1 * FO + c) =
                __floats2half2_rn(acc[nt][2], acc[nt][3]);
    }
}

// ---------------------------------------------------------------------------
// K scale: hs *= dinv (in place, fp32 math), tmp = hs (self-loop init).
// Thread = one 16B chunk (8 halves); 8 consecutive threads share one node.
__global__ __launch_bounds__(256) void k_scale(int N) {
    long i = (long)blockIdx.x * blockDim.x + threadIdx.x;
    if (i >= (long)N * 8) return;
    int node = (int)(i >> 3);
    long off = ((long)node * FO) + ((i & 7) << 3);
    float dinv = rsqrtf(g_deg[node]);
    uint4 v = *(const uint4*)(g_hs + off);
    __half2* h = (__half2*)&v;
    #pragma unroll
    for (int j = 0; j < 4; j++) {
        float2 f = __half22float2(h[j]);
        h[j] = __floats2half2_rn(f.x * dinv, f.y * dinv);
    }
    *(uint4*)(g_hs  + off) = v;
    *(uint4*)(g_tmp + off) = v;
}

// ---------------------------------------------------------------------------
// K scatter: tmp[dst] += hs[src] — 4 edges per warp-iteration, v4.f16x2 RED.
// (R13 config, proven at the L2 atomic line floor.)
__global__ __launch_bounds__(256) void k_scatter(const int* __restrict__ ei, int E) {
    int warp = (int)((blockIdx.x * blockDim.x + threadIdx.x) >> 5);
    int lane = threadIdx.x & 31;
    int e0 = warp << 5;
    if (e0 >= E) return;
    int n = E - e0; if (n > 32) n = 32;

    int mysrc = 0, mydst = 0;
    if (lane < n) {
        mysrc = __ldg(ei + e0 + lane);
        mydst = __ldg(ei + E + e0 + lane);
    }

    int sub = lane >> 3;
    int li  = lane & 7;

    int i = 0;
    #pragma unroll 2
    for (; i + 4 <= n; i += 4) {
        int src = __shfl_sync(0xFFFFFFFFu, mysrc, i + sub);
        int dst = __shfl_sync(0xFFFFFFFFu, mydst, i + sub);
        uint4 v = __ldg((const uint4*)(g_hs + (long)src * FO) + li);
        __half* p = g_tmp + (long)dst * FO + (li << 3);
        asm volatile("red.global.add.noftz.v4.f16x2 [%0], {%1, %2, %3, %4};"
                     :: "l"(p), "r"(v.x), "r"(v.y), "r"(v.z), "r"(v.w)
                     : "memory");
    }
    for (; i < n; i++) {
        int src = __shfl_sync(0xFFFFFFFFu, mysrc, i);
        int dst = __shfl_sync(0xFFFFFFFFu, mydst, i);
        unsigned hv = __ldg((const unsigned*)(g_hs + (long)src * FO) + lane);
        __half* p = g_tmp + (long)dst * FO + (lane << 1);
        asm volatile("red.global.add.noftz.f16x2 [%0], %1;"
                     :: "l"(p), "r"(hv) : "memory");
    }
}

// ---------------------------------------------------------------------------
// K final: out = sigmoid( relu(dinv*tmp + b_conv) . W_lin + b_lin )
__global__ void k_final(const float* __restrict__ Wl,
                        const float* __restrict__ bl,
                        const float* __restrict__ bconv,
                        float* __restrict__ out, int N) {
    int warp = (int)((blockIdx.x * blockDim.x + threadIdx.x) >> 5);
    int lane = threadIdx.x & 31;
    if (warp >= N) return;

    float dinv = rsqrtf(g_deg[warp]);
    __half2 th = *(const __half2*)&g_tmp[(long)warp * FO + lane * 2];
    float2 tv = __half22float2(th);
    float2 wv = *(const float2*)&Wl[lane * 2];
    float2 bc = *(const float2*)&bconv[lane * 2];

    float v0 = fmaxf(fmaf(tv.x, dinv, bc.x), 0.0f);
    float v1 = fmaxf(fmaf(tv.y, dinv, bc.y), 0.0f);
    float s  = v0 * wv.x + v1 * wv.y;

    #pragma unroll
    for (int o = 16; o; o >>= 1) s += __shfl_xor_sync(0xFFFFFFFFu, s, o);

    if (lane == 0) {
        float z = s + bl[0];
        out[warp] = 1.0f / (1.0f + expf(-z));
    }
}

// ---------------------------------------------------------------------------
extern "C" void kernel_launch(void* const* d_in, const int* in_sizes, int n_in,
                              void* d_out, int out_size) {
    const float* x   = (const float*)d_in[0];
    const int*   ei  = (const int*)  d_in[1];
    const float* Wc  = (const float*)d_in[2];
    const float* bc  = (const float*)d_in[3];
    const float* Wl  = (const float*)d_in[4];
    const float* bl  = (const float*)d_in[5];
    float*       out = (float*)d_out;

    int N = in_sizes[0] / FDIM;
    int E = in_sizes[1] / 2;
    if (N > NMAX) N = NMAX;

    const int GEMM_SMEM = (128 + 64) * SA * (int)sizeof(__half);   // 52224 B
    cudaFuncSetAttribute(k_gemm_h, cudaFuncAttributeMaxDynamicSharedMemorySize,
                         GEMM_SMEM);

    // fork/join: degree pass on s2 concurrent with the (degree-independent)
    // GEMM on the main stream. No device memory involved.
    cudaStream_t s2;
    cudaEvent_t ev_fork, ev_join;
    cudaStreamCreateWithFlags(&s2, cudaStreamNonBlocking);
    cudaEventCreateWithFlags(&ev_fork, cudaEventDisableTiming);
    cudaEventCreateWithFlags(&ev_join, cudaEventDisableTiming);

    cudaEventRecord(ev_fork, 0);
    cudaStreamWaitEvent(s2, ev_fork, 0);
    k_deg_init<<<(N + 255) / 256, 256, 0, s2>>>(N);
    k_deg_acc <<<((E + 3) / 4 + 255) / 256, 256, 0, s2>>>(ei, E);
    cudaEventRecord(ev_join, s2);

    k_gemm_h<<<(N + 127) / 128, 256, GEMM_SMEM>>>(x, Wc, N);

    cudaStreamWaitEvent(0, ev_join, 0);
    k_scale<<<((N * 8) + 255) / 256, 256>>>(N);
    {
        int nwarp  = (E + 31) / 32;
        int blocks = (nwarp + 7) / 8;
        k_scatter<<<blocks, 256>>>(ei, E);
    }
    k_final<<<(N + 7) / 8, 256>>>(Wl, bl, bc, out, N);
}

// round 16
// speedup vs baseline: 1.3396x; 1.0751x over previous
#include <cuda_runtime.h>
#include <cuda_fp16.h>
#include <cuda_bf16.h>

// Problem constants (from reference: N=100000, F=128, Fo=64, E=1600000)
#define NMAX 100000
#define FDIM 128
#define FO   64

__device__ __align__(16) float  g_deg[NMAX];
__device__ __align__(16) __half g_hs [NMAX * FO];  // fp16 messages h[i]*dinv[i]
__device__ __align__(16) __half g_tmp[NMAX * FO];  // fp16 aggregate (init = self loop)

// ---------------------------------------------------------------------------
__global__ void k_deg_init(int N) {
    int i = blockIdx.x * blockDim.x + threadIdx.x;
    if (i < N) g_deg[i] = 1.0f;
}

// PDL: trigger immediately so the (degree-independent) GEMM main phase can
// launch and overlap; our own dependence on k_deg_init is griddepsync'd.
__global__ void k_deg_acc(const int* __restrict__ ei, int E) {
    cudaTriggerProgrammaticLaunchCompletion();
    cudaGridDependencySynchronize();           // wait: g_deg initialized
    int t = blockIdx.x * blockDim.x + threadIdx.x;
    int e0 = t * 4;
    if (e0 + 3 < E) {
        int4 d = *(const int4*)(ei + E + e0);
        atomicAdd(&g_deg[d.x], 1.0f);
        atomicAdd(&g_deg[d.y], 1.0f);
        atomicAdd(&g_deg[d.z], 1.0f);
        atomicAdd(&g_deg[d.w], 1.0f);
    } else {
        for (int e = e0; e < E; e++) atomicAdd(&g_deg[ei[E + e]], 1.0f);
    }
}

// ---------------------------------------------------------------------------
// K gemm: hs/tmp (fp16) = (x @ W^T) * dinv via HMMA m16n8k16 (R12/R13 proven).
// PDL: whole load+MMA phase needs only x,W -> runs concurrently with
// k_deg_acc; griddepsync right before the epilogue reads g_deg.
#define SA 136

__global__ __launch_bounds__(256) void k_gemm(const float* __restrict__ x,
                                              const float* __restrict__ W,
                                              int N) {
    extern __shared__ __half smh[];
    __half* A_sh = smh;                 // [128][SA]
    __half* B_sh = smh + 128 * SA;      // [64][SA]

    int tid = threadIdx.x;
    int row0 = blockIdx.x * 128;

    #pragma unroll
    for (int i = tid; i < 64 * 32; i += 256) {
        int n  = i >> 5;
        int k4 = (i & 31) << 2;
        float4 v = *(const float4*)(W + n * FDIM + k4);
        __half* p = B_sh + n * SA + k4;
        *(__half2*)(p)     = __floats2half2_rn(v.x, v.y);
        *(__half2*)(p + 2) = __floats2half2_rn(v.z, v.w);
    }

    #pragma unroll
    for (int i = tid; i < 128 * 32; i += 256) {
        int r  = i >> 5;
        int k4 = (i & 31) << 2;
        int gr = row0 + r;
        float4 v = (gr < N) ? *(const float4*)(x + (long)gr * FDIM + k4)
                            : make_float4(0.f, 0.f, 0.f, 0.f);
        __half* p = A_sh + r * SA + k4;
        *(__half2*)(p)     = __floats2half2_rn(v.x, v.y);
        *(__half2*)(p + 2) = __floats2half2_rn(v.z, v.w);
    }
    __syncthreads();

    int warp = tid >> 5;
    int lane = tid & 31;
    int gid  = lane >> 2;
    int tig  = lane & 3;
    int mrow = warp * 16;

    float acc[8][4];
    #pragma unroll
    for (int nt = 0; nt < 8; nt++)
        #pragma unroll
        for (int j = 0; j < 4; j++) acc[nt][j] = 0.f;

    #pragma unroll
    for (int kt = 0; kt < 8; kt++) {
        int kb = kt * 16 + tig * 2;
        const __half* ar0 = A_sh + (mrow + gid) * SA + kb;
        const __half* ar1 = ar0 + 8 * SA;
        unsigned a0 = *(const unsigned*)(ar0);
        unsigned a1 = *(const unsigned*)(ar1);
        unsigned a2 = *(const unsigned*)(ar0 + 8);
        unsigned a3 = *(const unsigned*)(ar1 + 8);
        #pragma unroll
        for (int nt = 0; nt < 8; nt++) {
            const __half* br = B_sh + (nt * 8 + gid) * SA + kb;
            unsigned b0 = *(const unsigned*)(br);
            unsigned b1 = *(const unsigned*)(br + 8);
            asm("mma.sync.aligned.m16n8k16.row.col.f32.f16.f16.f32 "
                "{%0,%1,%2,%3}, {%4,%5,%6,%7}, {%8,%9}, {%0,%1,%2,%3};"
                : "+f"(acc[nt][0]), "+f"(acc[nt][1]),
                  "+f"(acc[nt][2]), "+f"(acc[nt][3])
                : "r"(a0), "r"(a1), "r"(a2), "r"(a3), "r"(b0), "r"(b1));
        }
    }

    // ---- dependence on the degree pass starts HERE ----
    cudaGridDependencySynchronize();

    int r0 = row0 + mrow + gid;
    int r1 = r0 + 8;
    float dinv0 = (r0 < N) ? rsqrtf(g_deg[r0]) : 0.f;
    float dinv1 = (r1 < N) ? rsqrtf(g_deg[r1]) : 0.f;
    #pragma unroll
    for (int nt = 0; nt < 8; nt++) {
        int c = nt * 8 + tig * 2;
        if (r0 < N) {
            __half2 h = __floats2half2_rn(acc[nt][0] * dinv0, acc[nt][1] * dinv0);
            long b = (long)r0 * FO + c;
            *(__half2*)(g_hs + b) = h;
            *(__half2*)(g_tmp + b) = h;
        }
        if (r1 < N) {
            __half2 h = __floats2half2_rn(acc[nt][2] * dinv1, acc[nt][3] * dinv1);
            long b = (long)r1 * FO + c;
            *(__half2*)(g_hs + b) = h;
            *(__half2*)(g_tmp + b) = h;
        }
    }
}

// ---------------------------------------------------------------------------
// K scatter: tmp[dst] += hs[src] — 4 edges/warp-iter, v4.f16x2 RED (R13).
// PDL: edge-index prologue is input-only; griddepsync before touching g_hs.
__global__ __launch_bounds__(256) void k_scatter(const int* __restrict__ ei, int E) {
    cudaTriggerProgrammaticLaunchCompletion();
    int warp = (int)((blockIdx.x * blockDim.x + threadIdx.x) >> 5);
    int lane = threadIdx.x & 31;
    int e0 = warp << 5;
    if (e0 >= E) { cudaGridDependencySynchronize(); return; }
    int n = E - e0; if (n > 32) n = 32;

    int mysrc = 0, mydst = 0;
    if (lane < n) {
        mysrc = __ldg(ei + e0 + lane);
        mydst = __ldg(ei + E + e0 + lane);
    }

    cudaGridDependencySynchronize();           // wait: g_hs / g_tmp ready

    int sub = lane >> 3;
    int li  = lane & 7;

    int i = 0;
    #pragma unroll 2
    for (; i + 4 <= n; i += 4) {
        int src = __shfl_sync(0xFFFFFFFFu, mysrc, i + sub);
        int dst = __shfl_sync(0xFFFFFFFFu, mydst, i + sub);
        uint4 v = __ldg((const uint4*)(g_hs + (long)src * FO) + li);
        __half* p = g_tmp + (long)dst * FO + (li << 3);
        asm volatile("red.global.add.noftz.v4.f16x2 [%0], {%1, %2, %3, %4};"
                     :: "l"(p), "r"(v.x), "r"(v.y), "r"(v.z), "r"(v.w)
                     : "memory");
    }
    for (; i < n; i++) {
        int src = __shfl_sync(0xFFFFFFFFu, mysrc, i);
        int dst = __shfl_sync(0xFFFFFFFFu, mydst, i);
        unsigned hv = __ldg((const unsigned*)(g_hs + (long)src * FO) + lane);
        __half* p = g_tmp + (long)dst * FO + (lane << 1);
        asm volatile("red.global.add.noftz.f16x2 [%0], %1;"
                     :: "l"(p), "r"(hv) : "memory");
    }
}

// ---------------------------------------------------------------------------
// K final: out = sigmoid( relu(dinv*tmp + b_conv) . W_lin + b_lin )
__global__ void k_final(const float* __restrict__ Wl,
                        const float* __restrict__ bl,
                        const float* __restrict__ bconv,
                        float* __restrict__ out, int N) {
    cudaGridDependencySynchronize();           // wait: all REDs done
    int warp = (int)((blockIdx.x * blockDim.x + threadIdx.x) >> 5);
    int lane = threadIdx.x & 31;
    if (warp >= N) return;

    float dinv = rsqrtf(g_deg[warp]);
    __half2 th = *(const __half2*)&g_tmp[(long)warp * FO + lane * 2];
    float2 tv = __half22float2(th);
    float2 wv = *(const float2*)&Wl[lane * 2];
    float2 bc = *(const float2*)&bconv[lane * 2];

    float v0 = fmaxf(fmaf(tv.x, dinv, bc.x), 0.0f);
    float v1 = fmaxf(fmaf(tv.y, dinv, bc.y), 0.0f);
    float s  = v0 * wv.x + v1 * wv.y;

    #pragma unroll
    for (int o = 16; o; o >>= 1) s += __shfl_xor_sync(0xFFFFFFFFu, s, o);

    if (lane == 0) {
        float z = s + bl[0];
        out[warp] = 1.0f / (1.0f + expf(-z));
    }
}

// ---------------------------------------------------------------------------
// Helper: launch with the PDL attribute set.
template <typename K, typename... Args>
static void pdl_launch(K kern, dim3 grid, dim3 block, size_t smem,
                       Args... args) {
    cudaLaunchConfig_t cfg = {};
    cfg.gridDim = grid;
    cfg.blockDim = block;
    cfg.dynamicSmemBytes = smem;
    cfg.stream = 0;
    cudaLaunchAttribute attr[1];
    attr[0].id = cudaLaunchAttributeProgrammaticStreamSerialization;
    attr[0].val.programmaticStreamSerializationAllowed = 1;
    cfg.attrs = attr;
    cfg.numAttrs = 1;
    cudaLaunchKernelEx(&cfg, kern, args...);
}

extern "C" void kernel_launch(void* const* d_in, const int* in_sizes, int n_in,
                              void* d_out, int out_size) {
    const float* x   = (const float*)d_in[0];
    const int*   ei  = (const int*)  d_in[1];
    const float* Wc  = (const float*)d_in[2];
    const float* bc  = (const float*)d_in[3];
    const float* Wl  = (const float*)d_in[4];
    const float* bl  = (const float*)d_in[5];
    float*       out = (float*)d_out;

    int N = in_sizes[0] / FDIM;
    int E = in_sizes[1] / 2;
    if (N > NMAX) N = NMAX;

    const int GEMM_SMEM = (128 + 64) * SA * (int)sizeof(__half);   // 52224 B
    cudaFuncSetAttribute(k_gemm, cudaFuncAttributeMaxDynamicSharedMemorySize,
                         GEMM_SMEM);

    k_deg_init<<<(N + 255) / 256, 256>>>(N);

    pdl_launch(k_deg_acc, dim3(((E + 3) / 4 + 255) / 256), dim3(256), 0,
               ei, E);
    pdl_launch(k_gemm, dim3((N + 127) / 128), dim3(256), (size_t)GEMM_SMEM,
               x, Wc, N);
    {
        int nwarp  = (E + 31) / 32;
        int blocks = (nwarp + 7) / 8;
        pdl_launch(k_scatter, dim3(blocks), dim3(256), 0, ei, E);
    }
    pdl_launch(k_final, dim3((N + 7) / 8), dim3(256), 0, Wl, bl, bc, out, N);
}

// round 17
// speedup vs baseline: 1.3490x; 1.0070x over previous
#include <cuda_runtime.h>
#include <cuda_fp16.h>
#include <cuda_bf16.h>

// Problem constants (from reference: N=100000, F=128, Fo=64, E=1600000)
#define NMAX 100000
#define FDIM 128
#define FO   64

__device__ int g_cnt[NMAX];                        // in-degree (no self loop)
__device__ __align__(16) __half g_hs [NMAX * FO];  // fp16 messages h[i]*dinv[i]
__device__ __align__(16) __half g_tmp[NMAX * FO];  // fp16 aggregate (init = self loop)

// ---------------------------------------------------------------------------
__global__ void k_zero(int N) {
    int i = blockIdx.x * blockDim.x + threadIdx.x;
    if (i < N) g_cnt[i] = 0;
}

// Degree count. SINGLE-WAVE grid (8 edges/thread -> 782 CTAs, ~5.3 CTAs/SM,
// 1352 thr/SM): every CTA is resident in wave 1, so the start-trigger fires
// from all CTAs immediately and the PDL-dependent GEMM launches and
// co-resides (its CTAs fit in the remaining thread slots).
__global__ __launch_bounds__(256) void k_deg_acc(const int* __restrict__ ei, int E) {
    cudaTriggerProgrammaticLaunchCompletion();
    cudaGridDependencySynchronize();           // wait: g_cnt zeroed
    int t = blockIdx.x * blockDim.x + threadIdx.x;
    int e0 = t * 8;
    if (e0 + 8 <= E) {
        int4 a = *(const int4*)(ei + E + e0);
        int4 b = *(const int4*)(ei + E + e0 + 4);
        atomicAdd(&g_cnt[a.x], 1);
        atomicAdd(&g_cnt[a.y], 1);
        atomicAdd(&g_cnt[a.z], 1);
        atomicAdd(&g_cnt[a.w], 1);
        atomicAdd(&g_cnt[b.x], 1);
        atomicAdd(&g_cnt[b.y], 1);
        atomicAdd(&g_cnt[b.z], 1);
        atomicAdd(&g_cnt[b.w], 1);
    } else {
        for (int e = e0; e < E; e++) atomicAdd(&g_cnt[ei[E + e]], 1);
    }
}

// ---------------------------------------------------------------------------
// K gemm: hs/tmp (fp16) = (x @ W^T) * dinv via HMMA m16n8k16 (proven config).
// Load+MMA phase needs only x,W -> overlaps with k_deg_acc; griddepsync
// right before the epilogue reads g_cnt.
#define SA 136

__global__ __launch_bounds__(256) void k_gemm(const float* __restrict__ x,
                                              const float* __restrict__ W,
                                              int N) {
    extern __shared__ __half smh[];
    __half* A_sh = smh;                 // [128][SA]
    __half* B_sh = smh + 128 * SA;      // [64][SA]

    int tid = threadIdx.x;
    int row0 = blockIdx.x * 128;

    #pragma unroll
    for (int i = tid; i < 64 * 32; i += 256) {
        int n  = i >> 5;
        int k4 = (i & 31) << 2;
        float4 v = *(const float4*)(W + n * FDIM + k4);
        __half* p = B_sh + n * SA + k4;
        *(__half2*)(p)     = __floats2half2_rn(v.x, v.y);
        *(__half2*)(p + 2) = __floats2half2_rn(v.z, v.w);
    }

    #pragma unroll
    for (int i = tid; i < 128 * 32; i += 256) {
        int r  = i >> 5;
        int k4 = (i & 31) << 2;
        int gr = row0 + r;
        float4 v = (gr < N) ? *(const float4*)(x + (long)gr * FDIM + k4)
                            : make_float4(0.f, 0.f, 0.f, 0.f);
        __half* p = A_sh + r * SA + k4;
        *(__half2*)(p)     = __floats2half2_rn(v.x, v.y);
        *(__half2*)(p + 2) = __floats2half2_rn(v.z, v.w);
    }
    __syncthreads();

    int warp = tid >> 5;
    int lane = tid & 31;
    int gid  = lane >> 2;
    int tig  = lane & 3;
    int mrow = warp * 16;

    float acc[8][4];
    #pragma unroll
    for (int nt = 0; nt < 8; nt++)
        #pragma unroll
        for (int j = 0; j < 4; j++) acc[nt][j] = 0.f;

    #pragma unroll
    for (int kt = 0; kt < 8; kt++) {
        int kb = kt * 16 + tig * 2;
        const __half* ar0 = A_sh + (mrow + gid) * SA + kb;
        const __half* ar1 = ar0 + 8 * SA;
        unsigned a0 = *(const unsigned*)(ar0);
        unsigned a1 = *(const unsigned*)(ar1);
        unsigned a2 = *(const unsigned*)(ar0 + 8);
        unsigned a3 = *(const unsigned*)(ar1 + 8);
        #pragma unroll
        for (int nt = 0; nt < 8; nt++) {
            const __half* br = B_sh + (nt * 8 + gid) * SA + kb;
            unsigned b0 = *(const unsigned*)(br);
            unsigned b1 = *(const unsigned*)(br + 8);
            asm("mma.sync.aligned.m16n8k16.row.col.f32.f16.f16.f32 "
                "{%0,%1,%2,%3}, {%4,%5,%6,%7}, {%8,%9}, {%0,%1,%2,%3};"
                : "+f"(acc[nt][0]), "+f"(acc[nt][1]),
                  "+f"(acc[nt][2]), "+f"(acc[nt][3])
                : "r"(a0), "r"(a1), "r"(a2), "r"(a3), "r"(b0), "r"(b1));
        }
    }

    // ---- dependence on the degree pass starts HERE ----
    cudaGridDependencySynchronize();

    int r0 = row0 + mrow + gid;
    int r1 = r0 + 8;
    float dinv0 = (r0 < N) ? rsqrtf((float)g_cnt[r0] + 1.0f) : 0.f;
    float dinv1 = (r1 < N) ? rsqrtf((float)g_cnt[r1] + 1.0f) : 0.f;
    #pragma unroll
    for (int nt = 0; nt < 8; nt++) {
        int c = nt * 8 + tig * 2;
        if (r0 < N) {
            __half2 h = __floats2half2_rn(acc[nt][0] * dinv0, acc[nt][1] * dinv0);
            long b = (long)r0 * FO + c;
            *(__half2*)(g_hs + b) = h;
            *(__half2*)(g_tmp + b) = h;
        }
        if (r1 < N) {
            __half2 h = __floats2half2_rn(acc[nt][2] * dinv1, acc[nt][3] * dinv1);
            long b = (long)r1 * FO + c;
            *(__half2*)(g_hs + b) = h;
            *(__half2*)(g_tmp + b) = h;
        }
    }
}

// ---------------------------------------------------------------------------
// K scatter: tmp[dst] += hs[src] — 4 edges/warp-iter, v4.f16x2 RED (proven,
// at the LTS byte floor). Edge-index prologue before the griddepsync.
__global__ __launch_bounds__(256) void k_scatter(const int* __restrict__ ei, int E) {
    cudaTriggerProgrammaticLaunchCompletion();
    int warp = (int)((blockIdx.x * blockDim.x + threadIdx.x) >> 5);
    int lane = threadIdx.x & 31;
    int e0 = warp << 5;
    if (e0 >= E) { cudaGridDependencySynchronize(); return; }
    int n = E - e0; if (n > 32) n = 32;

    int mysrc = 0, mydst = 0;
    if (lane < n) {
        mysrc = __ldg(ei + e0 + lane);
        mydst = __ldg(ei + E + e0 + lane);
    }

    cudaGridDependencySynchronize();           // wait: g_hs / g_tmp ready

    int sub = lane >> 3;
    int li  = lane & 7;

    int i = 0;
    #pragma unroll 2
    for (; i + 4 <= n; i += 4) {
        int src = __shfl_sync(0xFFFFFFFFu, mysrc, i + sub);
        int dst = __shfl_sync(0xFFFFFFFFu, mydst, i + sub);
        uint4 v = __ldg((const uint4*)(g_hs + (long)src * FO) + li);
        __half* p = g_tmp + (long)dst * FO + (li << 3);
        asm volatile("red.global.add.noftz.v4.f16x2 [%0], {%1, %2, %3, %4};"
                     :: "l"(p), "r"(v.x), "r"(v.y), "r"(v.z), "r"(v.w)
                     : "memory");
    }
    for (; i < n; i++) {
        int src = __shfl_sync(0xFFFFFFFFu, mysrc, i);
        int dst = __shfl_sync(0xFFFFFFFFu, mydst, i);
        unsigned hv = __ldg((const unsigned*)(g_hs + (long)src * FO) + lane);
        __half* p = g_tmp + (long)dst * FO + (lane << 1);
        asm volatile("red.global.add.noftz.f16x2 [%0], %1;"
                     :: "l"(p), "r"(hv) : "memory");
    }
}

// ---------------------------------------------------------------------------
// K final: out = sigmoid( relu(dinv*tmp + b_conv) . W_lin + b_lin )
__global__ void k_final(const float* __restrict__ Wl,
                        const float* __restrict__ bl,
                        const float* __restrict__ bconv,
                        float* __restrict__ out, int N) {
    cudaGridDependencySynchronize();           // wait: all REDs done
    int warp = (int)((blockIdx.x * blockDim.x + threadIdx.x) >> 5);
    int lane = threadIdx.x & 31;
    if (warp >= N) return;

    float dinv = rsqrtf((float)g_cnt[warp] + 1.0f);
    __half2 th = *(const __half2*)&g_tmp[(long)warp * FO + lane * 2];
    float2 tv = __half22float2(th);
    float2 wv = *(const float2*)&Wl[lane * 2];
    float2 bc = *(const float2*)&bconv[lane * 2];

    float v0 = fmaxf(fmaf(tv.x, dinv, bc.x), 0.0f);
    float v1 = fmaxf(fmaf(tv.y, dinv, bc.y), 0.0f);
    float s  = v0 * wv.x + v1 * wv.y;

    #pragma unroll
    for (int o = 16; o; o >>= 1) s += __shfl_xor_sync(0xFFFFFFFFu, s, o);

    if (lane == 0) {
        float z = s + bl[0];
        out[warp] = 1.0f / (1.0f + expf(-z));
    }
}

// ---------------------------------------------------------------------------
// Helper: launch with the PDL attribute set.
template <typename K, typename... Args>
static void pdl_launch(K kern, dim3 grid, dim3 block, size_t smem,
                       Args... args) {
    cudaLaunchConfig_t cfg = {};
    cfg.gridDim = grid;
    cfg.blockDim = block;
    cfg.dynamicSmemBytes = smem;
    cfg.stream = 0;
    cudaLaunchAttribute attr[1];
    attr[0].id = cudaLaunchAttributeProgrammaticStreamSerialization;
    attr[0].val.programmaticStreamSerializationAllowed = 1;
    cfg.attrs = attr;
    cfg.numAttrs = 1;
    cudaLaunchKernelEx(&cfg, kern, args...);
}

extern "C" void kernel_launch(void* const* d_in, const int* in_sizes, int n_in,
                              void* d_out, int out_size) {
    const float* x   = (const float*)d_in[0];
    const int*   ei  = (const int*)  d_in[1];
    const float* Wc  = (const float*)d_in[2];
    const float* bc  = (const float*)d_in[3];
    const float* Wl  = (const float*)d_in[4];
    const float* bl  = (const float*)d_in[5];
    float*       out = (float*)d_out;

    int N = in_sizes[0] / FDIM;
    int E = in_sizes[1] / 2;
    if (N > NMAX) N = NMAX;

    const int GEMM_SMEM = (128 + 64) * SA * (int)sizeof(__half);   // 52224 B
    cudaFuncSetAttribute(k_gemm, cudaFuncAttributeMaxDynamicSharedMemorySize,
                         GEMM_SMEM);

    k_zero<<<(N + 255) / 256, 256>>>(N);

    // single-wave degree pass (8 edges/thread) -> all CTAs trigger at start
    pdl_launch(k_deg_acc, dim3(((E + 7) / 8 + 255) / 256), dim3(256), 0,
               ei, E);
    // gemm launches immediately (PDL), co-resides with deg_acc, syncs in epilogue
    pdl_launch(k_gemm, dim3((N + 127) / 128), dim3(256), (size_t)GEMM_SMEM,
               x, Wc, N);
    {
        int nwarp  = (E + 31) / 32;
        int blocks = (nwarp + 7) / 8;
        pdl_launch(k_scatter, dim3(blocks), dim3(256), 0, ei, E);
    }
    pdl_launch(k_final, dim3((N + 7) / 8), dim3(256), 0, Wl, bl, bc, out, N);
}